// round 13
// baseline (speedup 1.0000x reference)
#include <cuda_runtime.h>
#include <cuda_bf16.h>
#include <cstdint>
#include <math.h>

// ViT self-attention, B=8, N=2048, E=768, single head, fp32 in/out.
// All GEMMs on warp-level tensor cores (mma.sync m16n8k16 bf16, fp32 accum)
// with split-bf16 (hi+lo) emulated fp32: D += Ahi*Bhi + Ahi*Blo + Alo*Bhi.
// R13: persistent GEMM — fixed grid (2 CTAs/SM), tile loop kills wave
// quantization. Mainloop = R11 (best measured).

// ---------------- dims / scratch ----------------
static constexpr int BB = 8, NN = 2048, EE = 768;
static constexpr int MM = BB * NN;                  // 16384
static constexpr int E2 = 2 * EE;                   // 1536
static constexpr int WW = EE * EE;
static constexpr int PERSIST_CTAS = 296;            // 148 SMs x 2 CTAs

__device__ __nv_bfloat16 g_xhi[MM * EE],  g_xlo[MM * EE];
__device__ __nv_bfloat16 g_wthi[4 * WW],  g_wtlo[4 * WW];
__device__ __nv_bfloat16 g_qkhi[MM * E2], g_qklo[MM * E2];       // q|k combined
__device__ __nv_bfloat16 g_vthi[BB * EE * NN], g_vtlo[BB * EE * NN];
__device__ float         g_s[(long long)BB * NN * NN];
__device__ __nv_bfloat16 g_athi[(long long)BB * NN * NN], g_atlo[(long long)BB * NN * NN];
__device__ __nv_bfloat16 g_aohi[MM * EE], g_aolo[MM * EE];

// ---------------- PTX helpers ----------------
__device__ __forceinline__ uint32_t smem_u32(const void* p) {
    uint32_t a;
    asm("{ .reg .u64 t; cvta.to.shared.u64 t, %1; cvt.u32.u64 %0, t; }" : "=r"(a) : "l"(p));
    return a;
}
__device__ __forceinline__ void ldsm_x4(uint32_t* r, uint32_t addr) {
    asm volatile("ldmatrix.sync.aligned.m8n8.x4.shared.b16 {%0,%1,%2,%3}, [%4];"
                 : "=r"(r[0]), "=r"(r[1]), "=r"(r[2]), "=r"(r[3]) : "r"(addr));
}
__device__ __forceinline__ void mma16816(float* d, const uint32_t* a, const uint32_t* b) {
    asm volatile(
        "mma.sync.aligned.m16n8k16.row.col.f32.bf16.bf16.f32 "
        "{%0,%1,%2,%3}, {%4,%5,%6,%7}, {%8,%9}, {%0,%1,%2,%3};"
        : "+f"(d[0]), "+f"(d[1]), "+f"(d[2]), "+f"(d[3])
        : "r"(a[0]), "r"(a[1]), "r"(a[2]), "r"(a[3]), "r"(b[0]), "r"(b[1]));
}
__device__ __forceinline__ void cp_async16(uint32_t saddr, const void* g) {
    asm volatile("cp.async.cg.shared.global [%0], [%1], 16;" :: "r"(saddr), "l"(g));
}
#define CP_COMMIT() asm volatile("cp.async.commit_group;" ::: "memory")
#define CP_WAIT(n)  asm volatile("cp.async.wait_group %0;" :: "n"(n) : "memory")

__device__ __forceinline__ float ex2(float x) {
    float r;
    asm("ex2.approx.ftz.f32 %0, %1;" : "=f"(r) : "f"(x));
    return r;
}

// Truncation hi/lo split for a float pair -> packed bf16x2 words.
__device__ __forceinline__ void split2(float v0, float v1, uint32_t& hi2, uint32_t& lo2) {
    const uint32_t x0 = __float_as_uint(v0), x1 = __float_as_uint(v1);
    hi2 = __byte_perm(x0, x1, 0x7632);
    const float l0 = v0 - __uint_as_float(x0 & 0xFFFF0000u);
    const float l1 = v1 - __uint_as_float(x1 & 0xFFFF0000u);
    asm("cvt.rn.bf16x2.f32 %0, %1, %2;" : "=r"(lo2) : "f"(l1), "f"(l0));
}

// ---------------- smem layout ----------------
static constexpr int SA_HI = 0;
static constexpr int SA_LO = 8192;
static constexpr int SB_HI = 16384;
static constexpr int SB_LO = 24576;
static constexpr int STAGE = 32768;
static constexpr int NSTAGE = 3;
static constexpr int SM_BYTES = NSTAGE * STAGE;   // 98304 (dynamic)

// ---------------- tensor-core GEMM (persistent) ----------------
// C[m,n] = alpha * sum_k A[m,k]*B[n,k] (+ bias), A/B split hi/lo bf16 K-major.
// CTA tile 128x128, BK=32, 3-stage cp.async pipeline, one barrier/chunk.
// 8 warps: 2(M)x4(N), warp tile 64x32. Persistent: grid=PERSIST_CTAS CTAs
// loop over ntx*nty*ntz tiles.
__global__ void __launch_bounds__(256, 2)
mma_gemm(const __nv_bfloat16* __restrict__ Ahi, const __nv_bfloat16* __restrict__ Alo,
         int lda, int strideA,
         const __nv_bfloat16* __restrict__ Bhi, const __nv_bfloat16* __restrict__ Blo,
         int ldb, int strideB,
         float* __restrict__ Cf32,
         __nv_bfloat16* __restrict__ Chi, __nv_bfloat16* __restrict__ Clo,
         int ldc, int strideC,
         int K, const float* __restrict__ bias, const float* __restrict__ bias2,
         int bias_row, float alpha,
         int ntx, int nty, int ntz)
{
    extern __shared__ __align__(16) char sm[];
    const uint32_t smb = smem_u32(sm);
    const int tid = threadIdx.x, wid = tid >> 5, lane = tid & 31;
    const int m_w = (wid >> 2) * 64;   // warp M offset (0,64)
    const int n_w = (wid & 3) * 32;    // warp N offset (0,32,64,96)

    // warp-position-dependent smem addressing (tile-independent)
    uint32_t aRowH[4], aRowL[4], aXor[4];
    uint32_t bRowH[2], bRowL[2], bXor[2];
    const uint32_t cA16 = ((uint32_t)(lane >> 4)) << 4;
    const uint32_t cB16 = ((uint32_t)((lane >> 3) & 1)) << 4;
    {
        const uint32_t ar = m_w + (lane & 15);
#pragma unroll
        for (int i = 0; i < 4; i++) {
            const uint32_t r = ar + i * 16;
            aRowH[i] = SA_HI + r * 64;
            aRowL[i] = SA_LO + r * 64;
            aXor[i] = ((r >> 1) & 3) << 4;
        }
        const uint32_t br = n_w + (lane & 7) + ((lane >> 4) & 1) * 8;
#pragma unroll
        for (int p = 0; p < 2; p++) {
            const uint32_t r = br + p * 16;
            bRowH[p] = SB_HI + r * 64;
            bRowL[p] = SB_LO + r * 64;
            bXor[p] = ((r >> 1) & 3) << 4;
        }
    }

    const int nch = K >> 5;
    const int ntiles = ntx * nty * ntz;

    for (int idx = blockIdx.x; idx < ntiles; idx += gridDim.x) {
        const int bx = idx % ntx;
        const int t2 = idx / ntx;
        const int by = t2 % nty;
        const int z  = t2 / nty;
        const int m0 = by * 128, n0 = bx * 128;

        const __nv_bfloat16* pAhi = Ahi + z * strideA;
        const __nv_bfloat16* pAlo = Alo + z * strideA;
        const __nv_bfloat16* pBhi = Bhi + z * strideB;
        const __nv_bfloat16* pBlo = Blo + z * strideB;

        float acc[4][4][4];
#pragma unroll
        for (int i = 0; i < 4; i++)
#pragma unroll
            for (int j = 0; j < 4; j++)
#pragma unroll
                for (int c = 0; c < 4; c++) acc[i][j][c] = 0.0f;

        auto issue = [&](int ck, int st) {
            const int kt = ck << 5;
            const uint32_t sb = smb + st * STAGE;
#pragma unroll
            for (int it = 0; it < 2; it++) {
                const int slot = tid + it * 256;
                const int r = slot >> 2;
                const int ch = slot & 3;
                const uint32_t so = (uint32_t)(r * 64 + ((ch ^ ((r >> 1) & 3)) << 4));
                const int ga = (m0 + r) * lda + kt + ch * 8;
                const int gb = (n0 + r) * ldb + kt + ch * 8;
                cp_async16(sb + SA_HI + so, pAhi + ga);
                cp_async16(sb + SA_LO + so, pAlo + ga);
                cp_async16(sb + SB_HI + so, pBhi + gb);
                cp_async16(sb + SB_LO + so, pBlo + gb);
            }
            CP_COMMIT();
        };

        issue(0, 0);
        issue(1, 1);

        int st = 0;
        for (int ck = 0; ck < nch; ck++) {
            if (ck + 2 < nch) { CP_WAIT(1); } else { CP_WAIT(0); }
            __syncthreads();
            if (ck + 2 < nch) {
                int st2 = st + 2; if (st2 >= NSTAGE) st2 -= NSTAGE;
                issue(ck + 2, st2);
            }

            const uint32_t sb = smb + st * STAGE;
#pragma unroll
            for (int kk = 0; kk < 2; kk++) {
                const uint32_t kk32 = kk * 32;
                uint32_t afH[4][4], afL[4][4], bfH[2][4], bfL[2][4];
#pragma unroll
                for (int i = 0; i < 4; i++)
                    ldsm_x4(afH[i], sb + aRowH[i] + ((kk32 + cA16) ^ aXor[i]));
#pragma unroll
                for (int p = 0; p < 2; p++)
                    ldsm_x4(bfH[p], sb + bRowH[p] + ((kk32 + cB16) ^ bXor[p]));
                // pass 1: Ahi * Bhi
#pragma unroll
                for (int i = 0; i < 4; i++)
#pragma unroll
                    for (int j = 0; j < 4; j++)
                        mma16816(acc[i][j], afH[i], &bfH[j >> 1][(j & 1) * 2]);
                // B-lo load (covered by pass 1)
#pragma unroll
                for (int p = 0; p < 2; p++)
                    ldsm_x4(bfL[p], sb + bRowL[p] + ((kk32 + cB16) ^ bXor[p]));
                // pass 2: Ahi * Blo
#pragma unroll
                for (int i = 0; i < 4; i++)
#pragma unroll
                    for (int j = 0; j < 4; j++)
                        mma16816(acc[i][j], afH[i], &bfL[j >> 1][(j & 1) * 2]);
                // A-lo load (covered by pass 2)
#pragma unroll
                for (int i = 0; i < 4; i++)
                    ldsm_x4(afL[i], sb + aRowL[i] + ((kk32 + cA16) ^ aXor[i]));
                // pass 3: Alo * Bhi
#pragma unroll
                for (int i = 0; i < 4; i++)
#pragma unroll
                    for (int j = 0; j < 4; j++)
                        mma16816(acc[i][j], afL[i], &bfH[j >> 1][(j & 1) * 2]);
            }
            st++; if (st >= NSTAGE) st = 0;
        }

        // all warps done reading smem for this tile before next tile's stores
        __syncthreads();

        // ---- epilogue ----
        const float* bcol = bias;
        if (bias && !bias_row && bias2 && n0 >= EE) bcol = bias2 - EE;
#pragma unroll
        for (int i = 0; i < 4; i++) {
#pragma unroll
            for (int h = 0; h < 2; h++) {
                const int row = m0 + m_w + i * 16 + (lane >> 2) + h * 8;
                const float brow = (bias && bias_row) ? bias[row] : 0.0f;
                const int rbase = z * strideC + row * ldc;
#pragma unroll
                for (int j = 0; j < 4; j++) {
                    const int col = n0 + n_w + j * 8 + 2 * (lane & 3);
                    float v0 = acc[i][j][h * 2 + 0] * alpha;
                    float v1 = acc[i][j][h * 2 + 1] * alpha;
                    if (bias) {
                        if (bias_row) { v0 += brow; v1 += brow; }
                        else          { v0 += bcol[col]; v1 += bcol[col + 1]; }
                    }
                    if (Cf32) {
                        float2 w; w.x = v0; w.y = v1;
                        *(float2*)(Cf32 + rbase + col) = w;
                    }
                    if (Chi) {
                        uint32_t hi2, lo2;
                        split2(v0, v1, hi2, lo2);
                        *(uint32_t*)(Chi + rbase + col) = hi2;
                        *(uint32_t*)(Clo + rbase + col) = lo2;
                    }
                }
            }
        }
    }
}

// ---------------- prep kernels ----------------
__global__ void __launch_bounds__(256)
wprep(const float* __restrict__ W0, const float* __restrict__ W1,
      const float* __restrict__ W2, const float* __restrict__ W3,
      __nv_bfloat16* __restrict__ hi, __nv_bfloat16* __restrict__ lo)
{
    __shared__ float t[32][33];
    const int zi = blockIdx.z;
    const float* W = (zi == 0) ? W0 : (zi == 1) ? W1 : (zi == 2) ? W2 : W3;
    uint16_t* H = (uint16_t*)hi + zi * WW;
    __nv_bfloat16* L = lo + zi * WW;
    const int bx = blockIdx.x * 32, by = blockIdx.y * 32;
    const int tx = threadIdx.x, ty = threadIdx.y;
#pragma unroll
    for (int i = 0; i < 32; i += 8)
        t[ty + i][tx] = W[(by + ty + i) * EE + bx + tx];
    __syncthreads();
#pragma unroll
    for (int i = 0; i < 32; i += 8) {
        const float v = t[tx][ty + i];
        const uint32_t vi = __float_as_uint(v);
        const int o = (bx + ty + i) * EE + by + tx;
        H[o] = (uint16_t)(vi >> 16);
        L[o] = __float2bfloat16(v - __uint_as_float(vi & 0xFFFF0000u));
    }
}

__global__ void __launch_bounds__(256)
xsplit(const float* __restrict__ x, __nv_bfloat16* __restrict__ hi,
       __nv_bfloat16* __restrict__ lo, int n4)
{
    const int i = blockIdx.x * blockDim.x + threadIdx.x;
    if (i >= n4) return;
    const float4 v = ((const float4*)x)[i];
    uint32_t h01, l01, h23, l23;
    split2(v.x, v.y, h01, l01);
    split2(v.z, v.w, h23, l23);
    uint2 hw; hw.x = h01; hw.y = h23;
    uint2 lw; lw.x = l01; lw.y = l23;
    ((uint2*)hi)[i] = hw;
    ((uint2*)lo)[i] = lw;
}

// Row softmax (2048 cols). Input pre-scaled by log2(e)/sqrt(E) -> exp2 domain.
__global__ void __launch_bounds__(256)
softmax_kernel(const float* __restrict__ S, __nv_bfloat16* __restrict__ Ahi,
               __nv_bfloat16* __restrict__ Alo)
{
    __shared__ float red[8];
    const long long row = blockIdx.x;
    const float2* p = (const float2*)(S + row * 2048ll);
    const int tid = threadIdx.x, lane = tid & 31, warp = tid >> 5;

    float2 v[4];
#pragma unroll
    for (int i = 0; i < 4; i++) v[i] = p[tid + 256 * i];

    float m = fmaxf(v[0].x, v[0].y);
#pragma unroll
    for (int i = 1; i < 4; i++) m = fmaxf(m, fmaxf(v[i].x, v[i].y));
#pragma unroll
    for (int o = 16; o > 0; o >>= 1) m = fmaxf(m, __shfl_xor_sync(0xffffffffu, m, o));
    if (lane == 0) red[warp] = m;
    __syncthreads();
    float bm = red[0];
#pragma unroll
    for (int w = 1; w < 8; w++) bm = fmaxf(bm, red[w]);

    float s = 0.0f;
#pragma unroll
    for (int i = 0; i < 4; i++) {
        v[i].x = ex2(v[i].x - bm);
        v[i].y = ex2(v[i].y - bm);
        s += v[i].x + v[i].y;
    }
#pragma unroll
    for (int o = 16; o > 0; o >>= 1) s += __shfl_xor_sync(0xffffffffu, s, o);
    __syncthreads();
    if (lane == 0) red[warp] = s;
    __syncthreads();
    float bs = red[0];
#pragma unroll
    for (int w = 1; w < 8; w++) bs += red[w];

    const float inv = 1.0f / bs;
    uint32_t* oh = (uint32_t*)Ahi + row * 1024ll;
    uint32_t* ol = (uint32_t*)Alo + row * 1024ll;
#pragma unroll
    for (int i = 0; i < 4; i++) {
        uint32_t hi2, lo2;
        split2(v[i].x * inv, v[i].y * inv, hi2, lo2);
        oh[tid + 256 * i] = hi2;
        ol[tid + 256 * i] = lo2;
    }
}

// ---------------- launch ----------------
static inline int pgrid(int ntiles) {
    return ntiles < PERSIST_CTAS ? ntiles : PERSIST_CTAS;
}

extern "C" void kernel_launch(void* const* d_in, const int* in_sizes, int n_in,
                              void* d_out, int out_size)
{
    const float* x  = (const float*)d_in[0];
    const float* Wq = (const float*)d_in[1];
    const float* bq = (const float*)d_in[2];
    const float* Wk = (const float*)d_in[3];
    const float* bk = (const float*)d_in[4];
    const float* Wv = (const float*)d_in[5];
    const float* bv = (const float*)d_in[6];
    const float* Wo = (const float*)d_in[7];
    const float* bo = (const float*)d_in[8];
    float* out = (float*)d_out;

    __nv_bfloat16 *xhi, *xlo, *wthi, *wtlo, *qkhi, *qklo;
    __nv_bfloat16 *vthi, *vtlo, *athi, *atlo, *aohi, *aolo;
    float* s;
    cudaGetSymbolAddress((void**)&xhi, g_xhi);   cudaGetSymbolAddress((void**)&xlo, g_xlo);
    cudaGetSymbolAddress((void**)&wthi, g_wthi); cudaGetSymbolAddress((void**)&wtlo, g_wtlo);
    cudaGetSymbolAddress((void**)&qkhi, g_qkhi); cudaGetSymbolAddress((void**)&qklo, g_qklo);
    cudaGetSymbolAddress((void**)&vthi, g_vthi); cudaGetSymbolAddress((void**)&vtlo, g_vtlo);
    cudaGetSymbolAddress((void**)&s, g_s);
    cudaGetSymbolAddress((void**)&athi, g_athi); cudaGetSymbolAddress((void**)&atlo, g_atlo);
    cudaGetSymbolAddress((void**)&aohi, g_aohi); cudaGetSymbolAddress((void**)&aolo, g_aolo);

    cudaFuncSetAttribute(mma_gemm, cudaFuncAttributeMaxDynamicSharedMemorySize, SM_BYTES);

    // exp(score/sqrt(E)) == exp2(score * log2e/sqrt(E)) -> fold into S2 alpha.
    const float scale = 1.4426950408889634f / sqrtf((float)EE);
    const int sNE = NN * EE;
    const int sNN = NN * NN;
    const int sQK = NN * E2;

    // P0: prep
    wprep<<<dim3(24, 24, 4), dim3(32, 8)>>>(Wq, Wk, Wv, Wo, wthi, wtlo);
    const int n4 = MM * EE / 4;
    xsplit<<<(n4 + 255) / 256, 256>>>(x, xhi, xlo, n4);

    // S1qk: merged q|k projection  (M=16384, N=1536, K=768) — tiles 12x128x1
    mma_gemm<<<pgrid(12 * 128), 256, SM_BYTES>>>(
        xhi, xlo, EE, 0, wthi, wtlo, EE, 0,
        nullptr, qkhi, qklo, E2, 0, EE, bq, bk, 0, 1.0f,
        12, 128, 1);

    // S1v: vT[f][t] per batch — tiles 16x6x8
    mma_gemm<<<pgrid(16 * 6 * 8), 256, SM_BYTES>>>(
        wthi + 2 * WW, wtlo + 2 * WW, EE, 0, xhi, xlo, EE, sNE,
        nullptr, vthi, vtlo, NN, EE * NN, EE, bv, nullptr, 1, 1.0f,
        16, 6, 8);

    // S2: scores = q @ k^T * (log2e/sqrt(E)) per batch — tiles 16x16x8
    mma_gemm<<<pgrid(16 * 16 * 8), 256, SM_BYTES>>>(
        qkhi, qklo, E2, sQK, qkhi + EE, qklo + EE, E2, sQK,
        s, nullptr, nullptr, NN, sNN, EE, nullptr, nullptr, 0, scale,
        16, 16, 8);

    // S3: softmax (exp2 domain) + truncation bf16 split
    softmax_kernel<<<MM, 256>>>(s, athi, atlo);

    // S4: ao = attn @ v per batch (K=2048) — tiles 6x16x8
    mma_gemm<<<pgrid(6 * 16 * 8), 256, SM_BYTES>>>(
        athi, atlo, NN, sNN, vthi, vtlo, NN, EE * NN,
        nullptr, aohi, aolo, EE, sNE, NN, nullptr, nullptr, 0, 1.0f,
        6, 16, 8);

    // S5: out = ao @ Wo^T + bo — tiles 6x128x1
    mma_gemm<<<pgrid(6 * 128), 256, SM_BYTES>>>(
        aohi, aolo, EE, 0, wthi + 3 * WW, wtlo + 3 * WW, EE, 0,
        out, nullptr, nullptr, EE, 0, EE, bo, nullptr, 0, 1.0f,
        6, 128, 1);
}

// round 15
// speedup vs baseline: 1.0919x; 1.0919x over previous
#include <cuda_runtime.h>
#include <cuda_bf16.h>
#include <cstdint>
#include <math.h>

// ViT self-attention, B=8, N=2048, E=768, single head, fp32 in/out.
// All GEMMs on warp-level tensor cores (mma.sync m16n8k16 bf16, fp32 accum)
// with split-bf16 (hi+lo) emulated fp32: D += Ahi*Bhi + Ahi*Blo + Alo*Bhi.
// R14: R11 baseline (best measured) + LDGSTS issue moved after pass-1 MMAs
// so the cp.async burst overlaps tensor-pipe drain instead of delaying ldsm.

// ---------------- dims / scratch ----------------
static constexpr int BB = 8, NN = 2048, EE = 768;
static constexpr int MM = BB * NN;                  // 16384
static constexpr int E2 = 2 * EE;                   // 1536
static constexpr int WW = EE * EE;

__device__ __nv_bfloat16 g_xhi[MM * EE],  g_xlo[MM * EE];
__device__ __nv_bfloat16 g_wthi[4 * WW],  g_wtlo[4 * WW];
__device__ __nv_bfloat16 g_qkhi[MM * E2], g_qklo[MM * E2];       // q|k combined
__device__ __nv_bfloat16 g_vthi[BB * EE * NN], g_vtlo[BB * EE * NN];
__device__ float         g_s[(long long)BB * NN * NN];
__device__ __nv_bfloat16 g_athi[(long long)BB * NN * NN], g_atlo[(long long)BB * NN * NN];
__device__ __nv_bfloat16 g_aohi[MM * EE], g_aolo[MM * EE];

// ---------------- PTX helpers ----------------
__device__ __forceinline__ uint32_t smem_u32(const void* p) {
    uint32_t a;
    asm("{ .reg .u64 t; cvta.to.shared.u64 t, %1; cvt.u32.u64 %0, t; }" : "=r"(a) : "l"(p));
    return a;
}
__device__ __forceinline__ void ldsm_x4(uint32_t* r, uint32_t addr) {
    asm volatile("ldmatrix.sync.aligned.m8n8.x4.shared.b16 {%0,%1,%2,%3}, [%4];"
                 : "=r"(r[0]), "=r"(r[1]), "=r"(r[2]), "=r"(r[3]) : "r"(addr));
}
__device__ __forceinline__ void mma16816(float* d, const uint32_t* a, const uint32_t* b) {
    asm volatile(
        "mma.sync.aligned.m16n8k16.row.col.f32.bf16.bf16.f32 "
        "{%0,%1,%2,%3}, {%4,%5,%6,%7}, {%8,%9}, {%0,%1,%2,%3};"
        : "+f"(d[0]), "+f"(d[1]), "+f"(d[2]), "+f"(d[3])
        : "r"(a[0]), "r"(a[1]), "r"(a[2]), "r"(a[3]), "r"(b[0]), "r"(b[1]));
}
__device__ __forceinline__ void cp_async16(uint32_t saddr, const void* g) {
    asm volatile("cp.async.cg.shared.global [%0], [%1], 16;" :: "r"(saddr), "l"(g));
}
#define CP_COMMIT() asm volatile("cp.async.commit_group;" ::: "memory")
#define CP_WAIT(n)  asm volatile("cp.async.wait_group %0;" :: "n"(n) : "memory")

__device__ __forceinline__ float ex2(float x) {
    float r;
    asm("ex2.approx.ftz.f32 %0, %1;" : "=f"(r) : "f"(x));
    return r;
}

// Truncation hi/lo split for a float pair -> packed bf16x2 words.
__device__ __forceinline__ void split2(float v0, float v1, uint32_t& hi2, uint32_t& lo2) {
    const uint32_t x0 = __float_as_uint(v0), x1 = __float_as_uint(v1);
    hi2 = __byte_perm(x0, x1, 0x7632);
    const float l0 = v0 - __uint_as_float(x0 & 0xFFFF0000u);
    const float l1 = v1 - __uint_as_float(x1 & 0xFFFF0000u);
    asm("cvt.rn.bf16x2.f32 %0, %1, %2;" : "=r"(lo2) : "f"(l1), "f"(l0));
}

// ---------------- smem layout ----------------
static constexpr int SA_HI = 0;
static constexpr int SA_LO = 8192;
static constexpr int SB_HI = 16384;
static constexpr int SB_LO = 24576;
static constexpr int STAGE = 32768;
static constexpr int NSTAGE = 3;
static constexpr int SM_BYTES = NSTAGE * STAGE;   // 98304 (dynamic)

// one 4-MMA column group
#define MMA_COL(A, B, j) \
    mma16816(acc[0][j], A[0], &B[j >> 1][(j & 1) * 2]); \
    mma16816(acc[1][j], A[1], &B[j >> 1][(j & 1) * 2]); \
    mma16816(acc[2][j], A[2], &B[j >> 1][(j & 1) * 2]); \
    mma16816(acc[3][j], A[3], &B[j >> 1][(j & 1) * 2]);

// ---------------- tensor-core GEMM ----------------
// C[m,n] = alpha * sum_k A[m,k]*B[n,k] (+ bias), A/B split hi/lo bf16 K-major.
// CTA tile 128x128, BK=32, 3-stage cp.async pipeline, one barrier/chunk.
// 8 warps: 2(M)x4(N), warp tile 64x32. Grid: (N/128, M/128, batch).
__global__ void __launch_bounds__(256, 2)
mma_gemm(const __nv_bfloat16* __restrict__ Ahi, const __nv_bfloat16* __restrict__ Alo,
         int lda, int strideA,
         const __nv_bfloat16* __restrict__ Bhi, const __nv_bfloat16* __restrict__ Blo,
         int ldb, int strideB,
         float* __restrict__ Cf32,
         __nv_bfloat16* __restrict__ Chi, __nv_bfloat16* __restrict__ Clo,
         int ldc, int strideC,
         int K, const float* __restrict__ bias, const float* __restrict__ bias2,
         int bias_row, float alpha)
{
    extern __shared__ __align__(16) char sm[];
    const uint32_t smb = smem_u32(sm);
    const int tid = threadIdx.x, wid = tid >> 5, lane = tid & 31;
    const int m0 = blockIdx.y * 128, n0 = blockIdx.x * 128;
    const int z = blockIdx.z;
    const int m_w = (wid >> 2) * 64;   // warp M offset (0,64)
    const int n_w = (wid & 3) * 32;    // warp N offset (0,32,64,96)

    Ahi += z * strideA; Alo += z * strideA;
    Bhi += z * strideB; Blo += z * strideB;

    // column-bias selector (merged q|k projection: cols >= 768 use bias2)
    const float* bcol = bias;
    if (bias && !bias_row && bias2 && n0 >= EE) bcol = bias2 - EE;

    uint32_t aRowH[4], aRowL[4], aXor[4];
    uint32_t bRowH[2], bRowL[2], bXor[2];
    const uint32_t cA16 = ((uint32_t)(lane >> 4)) << 4;
    const uint32_t cB16 = ((uint32_t)((lane >> 3) & 1)) << 4;
    {
        const uint32_t ar = m_w + (lane & 15);
#pragma unroll
        for (int i = 0; i < 4; i++) {
            const uint32_t r = ar + i * 16;
            aRowH[i] = SA_HI + r * 64;
            aRowL[i] = SA_LO + r * 64;
            aXor[i] = ((r >> 1) & 3) << 4;
        }
        const uint32_t br = n_w + (lane & 7) + ((lane >> 4) & 1) * 8;
#pragma unroll
        for (int p = 0; p < 2; p++) {
            const uint32_t r = br + p * 16;
            bRowH[p] = SB_HI + r * 64;
            bRowL[p] = SB_LO + r * 64;
            bXor[p] = ((r >> 1) & 3) << 4;
        }
    }

    float acc[4][4][4];
#pragma unroll
    for (int i = 0; i < 4; i++)
#pragma unroll
        for (int j = 0; j < 4; j++)
#pragma unroll
            for (int c = 0; c < 4; c++) acc[i][j][c] = 0.0f;

    const int nch = K >> 5;

    auto issue = [&](int ck, int st) {
        const int kt = ck << 5;
        const uint32_t sb = smb + st * STAGE;
#pragma unroll
        for (int it = 0; it < 2; it++) {
            const int slot = tid + it * 256;
            const int r = slot >> 2;
            const int ch = slot & 3;
            const uint32_t so = (uint32_t)(r * 64 + ((ch ^ ((r >> 1) & 3)) << 4));
            const int ga = (m0 + r) * lda + kt + ch * 8;
            const int gb = (n0 + r) * ldb + kt + ch * 8;
            cp_async16(sb + SA_HI + so, Ahi + ga);
            cp_async16(sb + SA_LO + so, Alo + ga);
            cp_async16(sb + SB_HI + so, Bhi + gb);
            cp_async16(sb + SB_LO + so, Blo + gb);
        }
        CP_COMMIT();
    };

    issue(0, 0);
    if (nch > 1) issue(1, 1);

    int st = 0;
    for (int ck = 0; ck < nch; ck++) {
        if (ck + 2 < nch) { CP_WAIT(1); } else { CP_WAIT(0); }
        __syncthreads();

        const uint32_t sb = smb + st * STAGE;
        #define AH(i, kk) (sb + aRowH[i] + ((((kk) << 5) + cA16) ^ aXor[i]))
        #define AL(i, kk) (sb + aRowL[i] + ((((kk) << 5) + cA16) ^ aXor[i]))
        #define BH(p, kk) (sb + bRowH[p] + ((((kk) << 5) + cB16) ^ bXor[p]))
        #define BL(p, kk) (sb + bRowL[p] + ((((kk) << 5) + cB16) ^ bXor[p]))

        uint32_t afH[4][4], afL[4][4], bfH[2][4], bfL[2][4];

        // ---- kk = 0 ----
        // fragments first: tensor pipe starts ASAP after the barrier
        ldsm_x4(afH[0], AH(0, 0)); ldsm_x4(afH[1], AH(1, 0));
        ldsm_x4(afH[2], AH(2, 0)); ldsm_x4(afH[3], AH(3, 0));
        ldsm_x4(bfH[0], BH(0, 0)); ldsm_x4(bfH[1], BH(1, 0));
        // pass 1: Ahi * Bhi
        MMA_COL(afH, bfH, 0); MMA_COL(afH, bfH, 1);
        MMA_COL(afH, bfH, 2); MMA_COL(afH, bfH, 3);
        // LDGSTS burst now — overlapped with tensor pipe draining pass 1
        if (ck + 2 < nch) {
            int st2 = st + 2; if (st2 >= NSTAGE) st2 -= NSTAGE;
            issue(ck + 2, st2);
        }
        // B-lo load, pass 2: Ahi * Blo
        ldsm_x4(bfL[0], BL(0, 0)); ldsm_x4(bfL[1], BL(1, 0));
        MMA_COL(afH, bfL, 0); MMA_COL(afH, bfL, 1);
        MMA_COL(afH, bfL, 2); MMA_COL(afH, bfL, 3);
        // A-lo load, pass 3: Alo * Bhi
        ldsm_x4(afL[0], AL(0, 0)); ldsm_x4(afL[1], AL(1, 0));
        ldsm_x4(afL[2], AL(2, 0)); ldsm_x4(afL[3], AL(3, 0));
        MMA_COL(afL, bfH, 0); MMA_COL(afL, bfH, 1);
        MMA_COL(afL, bfH, 2); MMA_COL(afL, bfH, 3);

        // ---- kk = 1 ----
        ldsm_x4(afH[0], AH(0, 1)); ldsm_x4(afH[1], AH(1, 1));
        ldsm_x4(afH[2], AH(2, 1)); ldsm_x4(afH[3], AH(3, 1));
        ldsm_x4(bfH[0], BH(0, 1)); ldsm_x4(bfH[1], BH(1, 1));
        MMA_COL(afH, bfH, 0); MMA_COL(afH, bfH, 1);
        MMA_COL(afH, bfH, 2); MMA_COL(afH, bfH, 3);
        ldsm_x4(bfL[0], BL(0, 1)); ldsm_x4(bfL[1], BL(1, 1));
        MMA_COL(afH, bfL, 0); MMA_COL(afH, bfL, 1);
        MMA_COL(afH, bfL, 2); MMA_COL(afH, bfL, 3);
        ldsm_x4(afL[0], AL(0, 1)); ldsm_x4(afL[1], AL(1, 1));
        ldsm_x4(afL[2], AL(2, 1)); ldsm_x4(afL[3], AL(3, 1));
        MMA_COL(afL, bfH, 0); MMA_COL(afL, bfH, 1);
        MMA_COL(afL, bfH, 2); MMA_COL(afL, bfH, 3);

        #undef AH
        #undef AL
        #undef BH
        #undef BL

        st++; if (st >= NSTAGE) st = 0;
    }

    // ---- epilogue ----
#pragma unroll
    for (int i = 0; i < 4; i++) {
#pragma unroll
        for (int h = 0; h < 2; h++) {
            const int row = m0 + m_w + i * 16 + (lane >> 2) + h * 8;
            const float brow = (bias && bias_row) ? bias[row] : 0.0f;
            const int rbase = z * strideC + row * ldc;
#pragma unroll
            for (int j = 0; j < 4; j++) {
                const int col = n0 + n_w + j * 8 + 2 * (lane & 3);
                float v0 = acc[i][j][h * 2 + 0] * alpha;
                float v1 = acc[i][j][h * 2 + 1] * alpha;
                if (bias) {
                    if (bias_row) { v0 += brow; v1 += brow; }
                    else          { v0 += bcol[col]; v1 += bcol[col + 1]; }
                }
                if (Cf32) {
                    float2 w; w.x = v0; w.y = v1;
                    *(float2*)(Cf32 + rbase + col) = w;
                }
                if (Chi) {
                    uint32_t hi2, lo2;
                    split2(v0, v1, hi2, lo2);
                    *(uint32_t*)(Chi + rbase + col) = hi2;
                    *(uint32_t*)(Clo + rbase + col) = lo2;
                }
            }
        }
    }
}

// ---------------- prep kernels ----------------
__global__ void __launch_bounds__(256)
wprep(const float* __restrict__ W0, const float* __restrict__ W1,
      const float* __restrict__ W2, const float* __restrict__ W3,
      __nv_bfloat16* __restrict__ hi, __nv_bfloat16* __restrict__ lo)
{
    __shared__ float t[32][33];
    const int zi = blockIdx.z;
    const float* W = (zi == 0) ? W0 : (zi == 1) ? W1 : (zi == 2) ? W2 : W3;
    uint16_t* H = (uint16_t*)hi + zi * WW;
    __nv_bfloat16* L = lo + zi * WW;
    const int bx = blockIdx.x * 32, by = blockIdx.y * 32;
    const int tx = threadIdx.x, ty = threadIdx.y;
#pragma unroll
    for (int i = 0; i < 32; i += 8)
        t[ty + i][tx] = W[(by + ty + i) * EE + bx + tx];
    __syncthreads();
#pragma unroll
    for (int i = 0; i < 32; i += 8) {
        const float v = t[tx][ty + i];
        const uint32_t vi = __float_as_uint(v);
        const int o = (bx + ty + i) * EE + by + tx;
        H[o] = (uint16_t)(vi >> 16);
        L[o] = __float2bfloat16(v - __uint_as_float(vi & 0xFFFF0000u));
    }
}

__global__ void __launch_bounds__(256)
xsplit(const float* __restrict__ x, __nv_bfloat16* __restrict__ hi,
       __nv_bfloat16* __restrict__ lo, int n4)
{
    const int i = blockIdx.x * blockDim.x + threadIdx.x;
    if (i >= n4) return;
    const float4 v = ((const float4*)x)[i];
    uint32_t h01, l01, h23, l23;
    split2(v.x, v.y, h01, l01);
    split2(v.z, v.w, h23, l23);
    uint2 hw; hw.x = h01; hw.y = h23;
    uint2 lw; lw.x = l01; lw.y = l23;
    ((uint2*)hi)[i] = hw;
    ((uint2*)lo)[i] = lw;
}

// Row softmax (2048 cols). Input pre-scaled by log2(e)/sqrt(E) -> exp2 domain.
__global__ void __launch_bounds__(256)
softmax_kernel(const float* __restrict__ S, __nv_bfloat16* __restrict__ Ahi,
               __nv_bfloat16* __restrict__ Alo)
{
    __shared__ float red[8];
    const long long row = blockIdx.x;
    const float2* p = (const float2*)(S + row * 2048ll);
    const int tid = threadIdx.x, lane = tid & 31, warp = tid >> 5;

    float2 v[4];
#pragma unroll
    for (int i = 0; i < 4; i++) v[i] = p[tid + 256 * i];

    float m = fmaxf(v[0].x, v[0].y);
#pragma unroll
    for (int i = 1; i < 4; i++) m = fmaxf(m, fmaxf(v[i].x, v[i].y));
#pragma unroll
    for (int o = 16; o > 0; o >>= 1) m = fmaxf(m, __shfl_xor_sync(0xffffffffu, m, o));
    if (lane == 0) red[warp] = m;
    __syncthreads();
    float bm = red[0];
#pragma unroll
    for (int w = 1; w < 8; w++) bm = fmaxf(bm, red[w]);

    float s = 0.0f;
#pragma unroll
    for (int i = 0; i < 4; i++) {
        v[i].x = ex2(v[i].x - bm);
        v[i].y = ex2(v[i].y - bm);
        s += v[i].x + v[i].y;
    }
#pragma unroll
    for (int o = 16; o > 0; o >>= 1) s += __shfl_xor_sync(0xffffffffu, s, o);
    __syncthreads();
    if (lane == 0) red[warp] = s;
    __syncthreads();
    float bs = red[0];
#pragma unroll
    for (int w = 1; w < 8; w++) bs += red[w];

    const float inv = 1.0f / bs;
    uint32_t* oh = (uint32_t*)Ahi + row * 1024ll;
    uint32_t* ol = (uint32_t*)Alo + row * 1024ll;
#pragma unroll
    for (int i = 0; i < 4; i++) {
        uint32_t hi2, lo2;
        split2(v[i].x * inv, v[i].y * inv, hi2, lo2);
        oh[tid + 256 * i] = hi2;
        ol[tid + 256 * i] = lo2;
    }
}

// ---------------- launch ----------------
extern "C" void kernel_launch(void* const* d_in, const int* in_sizes, int n_in,
                              void* d_out, int out_size)
{
    const float* x  = (const float*)d_in[0];
    const float* Wq = (const float*)d_in[1];
    const float* bq = (const float*)d_in[2];
    const float* Wk = (const float*)d_in[3];
    const float* bk = (const float*)d_in[4];
    const float* Wv = (const float*)d_in[5];
    const float* bv = (const float*)d_in[6];
    const float* Wo = (const float*)d_in[7];
    const float* bo = (const float*)d_in[8];
    float* out = (float*)d_out;

    __nv_bfloat16 *xhi, *xlo, *wthi, *wtlo, *qkhi, *qklo;
    __nv_bfloat16 *vthi, *vtlo, *athi, *atlo, *aohi, *aolo;
    float* s;
    cudaGetSymbolAddress((void**)&xhi, g_xhi);   cudaGetSymbolAddress((void**)&xlo, g_xlo);
    cudaGetSymbolAddress((void**)&wthi, g_wthi); cudaGetSymbolAddress((void**)&wtlo, g_wtlo);
    cudaGetSymbolAddress((void**)&qkhi, g_qkhi); cudaGetSymbolAddress((void**)&qklo, g_qklo);
    cudaGetSymbolAddress((void**)&vthi, g_vthi); cudaGetSymbolAddress((void**)&vtlo, g_vtlo);
    cudaGetSymbolAddress((void**)&s, g_s);
    cudaGetSymbolAddress((void**)&athi, g_athi); cudaGetSymbolAddress((void**)&atlo, g_atlo);
    cudaGetSymbolAddress((void**)&aohi, g_aohi); cudaGetSymbolAddress((void**)&aolo, g_aolo);

    cudaFuncSetAttribute(mma_gemm, cudaFuncAttributeMaxDynamicSharedMemorySize, SM_BYTES);

    // exp(score/sqrt(E)) == exp2(score * log2e/sqrt(E)) -> fold into S2 alpha.
    const float scale = 1.4426950408889634f / sqrtf((float)EE);
    const int sNE = NN * EE;
    const int sNN = NN * NN;
    const int sQK = NN * E2;

    // P0: prep
    wprep<<<dim3(24, 24, 4), dim3(32, 8)>>>(Wq, Wk, Wv, Wo, wthi, wtlo);
    const int n4 = MM * EE / 4;
    xsplit<<<(n4 + 255) / 256, 256>>>(x, xhi, xlo, n4);

    // S1qk: merged q|k projection  (M=16384, N=1536, K=768)
    mma_gemm<<<dim3(12, 128, 1), 256, SM_BYTES>>>(
        xhi, xlo, EE, 0, wthi, wtlo, EE, 0,
        nullptr, qkhi, qklo, E2, 0, EE, bq, bk, 0, 1.0f);

    // S1v: vT[f][t] per batch  (A=WvT [768,768], B=x rows of batch, bias per-row)
    mma_gemm<<<dim3(16, 6, 8), 256, SM_BYTES>>>(
        wthi + 2 * WW, wtlo + 2 * WW, EE, 0, xhi, xlo, EE, sNE,
        nullptr, vthi, vtlo, NN, EE * NN, EE, bv, nullptr, 1, 1.0f);

    // S2: scores = q @ k^T * (log2e/sqrt(E)) per batch  (M=N=2048, K=768)
    mma_gemm<<<dim3(16, 16, 8), 256, SM_BYTES>>>(
        qkhi, qklo, E2, sQK, qkhi + EE, qklo + EE, E2, sQK,
        s, nullptr, nullptr, NN, sNN, EE, nullptr, nullptr, 0, scale);

    // S3: softmax (exp2 domain) + truncation bf16 split
    softmax_kernel<<<MM, 256>>>(s, athi, atlo);

    // S4: ao = attn @ v per batch  (M=2048, N=768, K=2048), B = vT K-major
    mma_gemm<<<dim3(6, 16, 8), 256, SM_BYTES>>>(
        athi, atlo, NN, sNN, vthi, vtlo, NN, EE * NN,
        nullptr, aohi, aolo, EE, sNE, NN, nullptr, nullptr, 0, 1.0f);

    // S5: out = ao @ Wo^T + bo
    mma_gemm<<<dim3(6, 128, 1), 256, SM_BYTES>>>(
        aohi, aolo, EE, 0, wthi + 3 * WW, wtlo + 3 * WW, EE, 0,
        out, nullptr, nullptr, EE, 0, EE, bo, nullptr, 0, 1.0f);
}